// round 15
// baseline (speedup 1.0000x reference)
#include <cuda_runtime.h>
#include <cstdint>

#define NN 16000
#define EE 512000
#define CC 32
#define SHD 9
#define NLAYERS 3
#define NGRAPHS 40
#define TBINS 2200          // bins over [0,5]; knots 5k/11 align at i=200k
#define TSCALE 440.0f       // TBINS/5
#define WPB 8               // warps (nodes) per block in aggnode

// combo kernel block ranges
#define TAB_BLOCKS 23       // ceil(3*2201/288)
#define HIST_BLOCKS 1778    // ceil(EE/288)

// ---------------- device scratch --------------------------------------------
__device__ float g_bufA[NN * SHD * CC];                  // node state ping (18.4 MB)
__device__ float g_bufB[NN * SHD * CC];                  // node state pong (18.4 MB)
// per-edge payload struct, PERMUTED by dst: 16 floats =
// [0:4) attr, [4:13) sh, [13] d, [14] src(bits), [15] pad          (32 MB)
__device__ float g_ep[(size_t)EE * 16];
__device__ float g_tab[NLAYERS * (TBINS + 1) * CC];      // radial tables (0.85 MB)
__device__ int   g_cnt[NN];
__device__ int   g_off[NN + 1];
__device__ int   g_cur[NN];
__device__ int   g_bsum[16];

// ---------------- helpers ---------------------------------------------------
__device__ __forceinline__ float fast_silu(float x) {
    return __fdividef(x, 1.0f + __expf(-x));
}

__device__ __forceinline__ void compute_sh(float vx, float vy, float vz, float* shv) {
    float r2 = vx * vx + vy * vy + vz * vz + 1e-12f;
    float rinv = rsqrtf(r2);
    float x = vx * rinv, y = vy * rinv, z = vz * rinv;
    const float s3    = 1.7320508075688772f;
    const float s15   = 3.872983346207417f;
    const float s5_4  = 1.118033988749895f;    // sqrt(5)/2
    const float s15_4 = 1.9364916731037085f;   // sqrt(15)/2
    shv[0] = 1.0f;
    shv[1] = s3 * x;
    shv[2] = s3 * y;
    shv[3] = s3 * z;
    shv[4] = s15 * x * y;
    shv[5] = s15 * y * z;
    shv[6] = s5_4 * (3.0f * z * z - 1.0f);
    shv[7] = s15 * z * x;
    shv[8] = s15_4 * (x * x - y * y);
}

__device__ __forceinline__ void compute_emb(float d, float* emb) {
    const float stepinv = 11.0f / 5.0f;
    const float SQNB = 3.1622776601683795f;   // sqrt(10)
    const float HPI = 1.5707963267948966f;
    #pragma unroll
    for (int i = 0; i < 10; i++) {
        float center = (5.0f / 11.0f) * (float)(i + 1);
        float diff = (d - center) * stepinv;
        float v = 0.0f;
        if (diff > -1.0f && diff < 1.0f) v = __cosf(HPI * diff) * SQNB;
        emb[i] = v;
    }
}

// ---------------- kernel 1: fused tin + tab + hist ---------------------------
__global__ __launch_bounds__(288) void combo_kernel(
        const float* __restrict__ node_input,
        const float* __restrict__ W1,
        const float* __restrict__ b1,
        const float* __restrict__ W2,
        const int* __restrict__ eidx) {
    __shared__ float sm[288];
    int b = blockIdx.x;
    int t = threadIdx.x;

    if (b < NN) {
        sm[t] = node_input[b * 288 + t];      // [c][k], linear
        __syncthreads();
        int k = t >> 5, c = t & 31;
        g_bufA[(b * SHD + k) * CC + c] = sm[c * SHD + k];
        return;
    }
    b -= NN;
    if (b < TAB_BLOCKS) {
        int idx = b * 288 + t;
        if (idx >= 3 * (TBINS + 1)) return;
        int l = idx / (TBINS + 1);
        int bin = idx % (TBINS + 1);
        float d = (float)bin * (5.0f / (float)TBINS);
        float emb[10];
        compute_emb(d, emb);
        float w[32];
        #pragma unroll
        for (int c = 0; c < 32; c++) w[c] = 0.0f;
        for (int j = 0; j < 100; j++) {
            float h = b1[l * 100 + j];
            #pragma unroll
            for (int i = 0; i < 10; i++) h += emb[i] * W1[l * 1000 + i * 100 + j];
            h = fast_silu(h);
            const float* w2r = &W2[l * 3200 + j * 32];
            #pragma unroll
            for (int c = 0; c < 32; c++) w[c] += h * w2r[c];
        }
        const float INVS32 = 0.17677669529663687f;  // fold 1/sqrt(32)
        float* out = &g_tab[((size_t)l * (TBINS + 1) + bin) * 32];
        #pragma unroll
        for (int c = 0; c < 32; c++) out[c] = w[c] * INVS32;
        return;
    }
    b -= TAB_BLOCKS;
    int e = b * 288 + t;
    if (e < EE) atomicAdd(&g_cnt[eidx[e]], 1);
}

// ---------------- scan (two-kernel, measured ~10us) --------------------------
__global__ void scan1_kernel() {
    __shared__ int wsum[32];
    int tid = threadIdx.x;
    int b = blockIdx.x;
    int i = b * 1024 + tid;
    int v = (i < NN) ? g_cnt[i] : 0;
    int lane = tid & 31, wid = tid >> 5;
    int x = v;
    #pragma unroll
    for (int o = 1; o < 32; o <<= 1) {
        int t = __shfl_up_sync(0xffffffffu, x, o);
        if (lane >= o) x += t;
    }
    if (lane == 31) wsum[wid] = x;
    __syncthreads();
    if (wid == 0) {
        int y = wsum[lane];
        #pragma unroll
        for (int o = 1; o < 32; o <<= 1) {
            int t = __shfl_up_sync(0xffffffffu, y, o);
            if (lane >= o) y += t;
        }
        wsum[lane] = y;
    }
    __syncthreads();
    int incl = x + ((wid > 0) ? wsum[wid - 1] : 0);
    if (i < NN) g_off[i] = incl - v;
    if (tid == 1023) g_bsum[b] = incl;
}

__global__ void scan23_kernel() {
    __shared__ int addv;
    int b = blockIdx.x;
    if (threadIdx.x == 0) {
        int s = 0;
        for (int i = 0; i < b; i++) s += g_bsum[i];
        addv = s;
    }
    __syncthreads();
    int i = b * 1024 + threadIdx.x;
    if (i < NN) {
        int o = g_off[i] + addv;
        g_off[i] = o;
        g_cur[i] = o;
    }
    if (i == 0) g_off[NN] = EE;
}

// ---------------- scatter + permuted payload (64B struct, 4x STG.128) --------
__global__ __launch_bounds__(256) void scatterprep_kernel(
        const int* __restrict__ eidx,
        const float* __restrict__ edge_vec,
        const float* __restrict__ edge_attr) {
    int e = blockIdx.x * 256 + threadIdx.x;
    if (e >= EE) return;
    int dnode = eidx[e];
    int src = eidx[EE + e];
    float vx = edge_vec[3 * e + 0];
    float vy = edge_vec[3 * e + 1];
    float vz = edge_vec[3 * e + 2];
    float d = sqrtf(vx * vx + vy * vy + vz * vz + 1e-12f);
    float shv[9];
    compute_sh(vx, vy, vz, shv);
    float4 a4 = *(const float4*)(edge_attr + 4 * e);
    int pos = atomicAdd(&g_cur[dnode], 1);
    float4* dst = (float4*)(g_ep + (size_t)pos * 16);
    dst[0] = a4;
    dst[1] = make_float4(shv[0], shv[1], shv[2], shv[3]);
    dst[2] = make_float4(shv[4], shv[5], shv[6], shv[7]);
    dst[3] = make_float4(shv[8], d, __int_as_float(src), 0.0f);
}

// ---------------- fused edge-weight + aggregate + node update ---------------
// One warp per node, lanes = channels c. 4 blocks/SM (64-reg cap; Wattr in smem).
// Payload: uniform broadcast loads for at/d/src; lane<9 + shfl for sh.
__global__ __launch_bounds__(32 * WPB, 4) void aggnode_kernel(
        const float* __restrict__ node_attr,
        const float* __restrict__ Wself,
        const float* __restrict__ Wout,
        const float* __restrict__ Wattr,
        const float* __restrict__ xin,
        float* __restrict__ xout,
        int l) {
    __shared__ float sWs[1024], sWo[1024], sWa[416];
    __shared__ float sX[WPB][9][32];
    __shared__ float sA[WPB][9][32];

    int t = threadIdx.x;
    int lane = t & 31;
    int wid = t >> 5;
    for (int i = t; i < 1024; i += 32 * WPB) {
        sWs[i] = Wself[l * 1024 + i];
        sWo[i] = Wout[l * 1024 + i];
    }
    for (int i = t; i < 416; i += 32 * WPB) sWa[i] = Wattr[l * 416 + i];
    __syncthreads();

    int n = blockIdx.x * WPB + wid;

    const float* tabL = g_tab + (size_t)l * (TBINS + 1) * 32;
    int j0 = g_off[n];
    int j1 = g_off[n + 1];

    float acc[9];
    #pragma unroll
    for (int k = 0; k < 9; k++) acc[k] = 0.0f;

    #pragma unroll 2
    for (int j = j0; j < j1; j++) {
        const float* epj = g_ep + (size_t)j * 16;
        float4 at = *(const float4*)epj;            // uniform broadcast
        float sh9 = (lane < 9) ? epj[4 + lane] : 0.0f;
        float d = epj[13];                          // uniform broadcast
        int src = __float_as_int(epj[14]);          // uniform broadcast

        float shk[9];
        #pragma unroll
        for (int k = 0; k < 9; k++) shk[k] = __shfl_sync(0xffffffffu, sh9, k);

        // aw[lane] = ea @ Wattr  (ea = [attr4, sh9]); weights from shared
        float aw = at.x * sWa[lane];
        aw = fmaf(at.y, sWa[32 + lane], aw);
        aw = fmaf(at.z, sWa[64 + lane], aw);
        aw = fmaf(at.w, sWa[96 + lane], aw);
        #pragma unroll
        for (int k = 0; k < 9; k++) aw = fmaf(shk[k], sWa[(4 + k) * 32 + lane], aw);

        // radial lerp (includes 1/sqrt(32)); branch-free clamp, exact at d>=5
        float u = fminf(d * TSCALE, (float)TBINS);
        int i0 = min((int)u, TBINS - 1);
        float f = u - (float)i0;
        float a = tabL[i0 * 32 + lane];
        float b = tabL[(i0 + 1) * 32 + lane];
        float w = fmaf(f, b - a, a) * aw;

        const float* xr = xin + (size_t)src * 288 + lane;
        #pragma unroll
        for (int k = 0; k < 9; k++)
            acc[k] = fmaf(xr[k * 32], shk[k] * w, acc[k]);
    }

    // stash aggregate, then load self features (coalesced) for phase 2
    #pragma unroll
    for (int k = 0; k < 9; k++) sA[wid][k][lane] = acc[k];
    {
        const float* xself = xin + (size_t)n * 288 + lane;
        #pragma unroll
        for (int k = 0; k < 9; k++) sX[wid][k][lane] = xself[k * 32];
    }
    __syncwarp();

    // phase 2: per-warp 32x32 mixes + gating (lane = d)
    float na = node_attr[n];
    float val[9];
    #pragma unroll
    for (int k = 0; k < 9; k++) {
        float aS = 0.0f, aA = 0.0f;
        #pragma unroll
        for (int c = 0; c < 32; c++) {
            aS = fmaf(sX[wid][k][c], sWs[c * 32 + lane], aS);
            aA = fmaf(sA[wid][k][c], sWo[c * 32 + lane], aA);
        }
        val[k] = na * aS + aA;
    }
    float sig = __fdividef(1.0f, 1.0f + __expf(-val[0]));
    float* outr = xout + (size_t)n * 288 + lane;
    outr[0] = val[0] * sig;
    #pragma unroll
    for (int k = 1; k < 9; k++) outr[k * 32] = val[k] * sig;
}

// ---------------- output reduction ------------------------------------------
__global__ __launch_bounds__(288) void out_kernel(const int* __restrict__ batch,
                                                  const float* __restrict__ xfin,
                                                  float* __restrict__ out) {
    int t = threadIdx.x;
    int k = t >> 5;             // warp reads contiguous c
    int c = t & 31;
    int n0 = blockIdx.x * 64;
    int n1 = n0 + 64;
    if (n1 > NN) n1 = NN;
    float acc = 0.0f;
    int curg = batch[n0];
    const float INVS400 = 0.05f;  // 1/sqrt(400)
    for (int n = n0; n < n1; n++) {
        int g = batch[n];
        if (g != curg) {
            atomicAdd(&out[curg * 288 + c * 9 + k], acc * INVS400);
            acc = 0.0f;
            curg = g;
        }
        acc += xfin[(n * SHD + k) * CC + c];
    }
    atomicAdd(&out[curg * 288 + c * 9 + k], acc * INVS400);
}

// ---------------- launch ----------------------------------------------------
extern "C" void kernel_launch(void* const* d_in, const int* in_sizes, int n_in,
                              void* d_out, int out_size) {
    const float* node_input = (const float*)d_in[0];
    const float* node_attr  = (const float*)d_in[1];
    const float* edge_vec   = (const float*)d_in[2];
    const float* edge_attr  = (const float*)d_in[3];
    const float* W1         = (const float*)d_in[4];
    const float* b1         = (const float*)d_in[5];
    const float* W2         = (const float*)d_in[6];
    const float* Wattr      = (const float*)d_in[7];
    const float* Wself      = (const float*)d_in[8];
    const float* Wout       = (const float*)d_in[9];
    const int*   eidx       = (const int*)d_in[10];
    const int*   batch      = (const int*)d_in[11];
    float* out = (float*)d_out;

    float* bufA; cudaGetSymbolAddress((void**)&bufA, g_bufA);
    float* bufB; cudaGetSymbolAddress((void**)&bufB, g_bufB);
    int*   cntp; cudaGetSymbolAddress((void**)&cntp, g_cnt);

    cudaMemsetAsync(cntp, 0, NN * sizeof(int));

    // #1: fused transpose + radial tables + histogram
    combo_kernel<<<NN + TAB_BLOCKS + HIST_BLOCKS, 288>>>(node_input, W1, b1, W2, eidx);
    // #2,#3: exclusive scan of degrees
    scan1_kernel<<<16, 1024>>>();
    scan23_kernel<<<16, 1024>>>();
    // #4: scatter + permuted 64B payload structs
    scatterprep_kernel<<<(EE + 255) / 256, 256>>>(eidx, edge_vec, edge_attr);

    float* xin = bufA;
    float* xout = bufB;
    for (int l = 0; l < NLAYERS; l++) {
        aggnode_kernel<<<NN / WPB, 32 * WPB>>>(node_attr, Wself, Wout, Wattr,
                                               xin, xout, l);
        float* tmp = xin; xin = xout; xout = tmp;
    }

    cudaMemsetAsync(out, 0, (size_t)out_size * sizeof(float));
    out_kernel<<<(NN + 63) / 64, 288>>>(batch, xin, out);
}

// round 16
// speedup vs baseline: 1.1499x; 1.1499x over previous
#include <cuda_runtime.h>
#include <cstdint>

#define NN 16000
#define EE 512000
#define CC 32
#define SHD 9
#define NLAYERS 3
#define NGRAPHS 40
#define TBINS 2200          // bins over [0,5]; knots 5k/11 align at i=200k
#define TSCALE 440.0f       // TBINS/5
#define WPB 8               // warps (nodes) per block in aggnode

// combo kernel block ranges
#define TAB_BLOCKS 23       // ceil(3*2201/288)
#define HIST_BLOCKS 1778    // ceil(EE/288)

// ---------------- device scratch --------------------------------------------
__device__ float g_bufA[NN * SHD * CC];                  // node state ping (18.4 MB)
__device__ float g_bufB[NN * SHD * CC];                  // node state pong (18.4 MB)
// per-edge payload struct, PERMUTED by dst: 16 floats =
// [0:4) attr, [4:13) sh, [13] d, [14] src(bits), [15] pad          (32 MB)
__device__ float g_ep[(size_t)EE * 16];
__device__ float g_tab[NLAYERS * (TBINS + 1) * CC];      // radial tables (0.85 MB)
__device__ int   g_cnt[NN];
__device__ int   g_off[NN + 1];
__device__ int   g_cur[NN];
__device__ int   g_bsum[16];

// ---------------- helpers ---------------------------------------------------
__device__ __forceinline__ float fast_silu(float x) {
    return __fdividef(x, 1.0f + __expf(-x));
}

__device__ __forceinline__ void compute_sh(float vx, float vy, float vz, float* shv) {
    float r2 = vx * vx + vy * vy + vz * vz + 1e-12f;
    float rinv = rsqrtf(r2);
    float x = vx * rinv, y = vy * rinv, z = vz * rinv;
    const float s3    = 1.7320508075688772f;
    const float s15   = 3.872983346207417f;
    const float s5_4  = 1.118033988749895f;    // sqrt(5)/2
    const float s15_4 = 1.9364916731037085f;   // sqrt(15)/2
    shv[0] = 1.0f;
    shv[1] = s3 * x;
    shv[2] = s3 * y;
    shv[3] = s3 * z;
    shv[4] = s15 * x * y;
    shv[5] = s15 * y * z;
    shv[6] = s5_4 * (3.0f * z * z - 1.0f);
    shv[7] = s15 * z * x;
    shv[8] = s15_4 * (x * x - y * y);
}

__device__ __forceinline__ void compute_emb(float d, float* emb) {
    const float stepinv = 11.0f / 5.0f;
    const float SQNB = 3.1622776601683795f;   // sqrt(10)
    const float HPI = 1.5707963267948966f;
    #pragma unroll
    for (int i = 0; i < 10; i++) {
        float center = (5.0f / 11.0f) * (float)(i + 1);
        float diff = (d - center) * stepinv;
        float v = 0.0f;
        if (diff > -1.0f && diff < 1.0f) v = __cosf(HPI * diff) * SQNB;
        emb[i] = v;
    }
}

// ---------------- kernel 1: fused tin + tab + hist ---------------------------
__global__ __launch_bounds__(288) void combo_kernel(
        const float* __restrict__ node_input,
        const float* __restrict__ W1,
        const float* __restrict__ b1,
        const float* __restrict__ W2,
        const int* __restrict__ eidx) {
    __shared__ float sm[288];
    int b = blockIdx.x;
    int t = threadIdx.x;

    if (b < NN) {
        sm[t] = node_input[b * 288 + t];      // [c][k], linear
        __syncthreads();
        int k = t >> 5, c = t & 31;
        g_bufA[(b * SHD + k) * CC + c] = sm[c * SHD + k];
        return;
    }
    b -= NN;
    if (b < TAB_BLOCKS) {
        int idx = b * 288 + t;
        if (idx >= 3 * (TBINS + 1)) return;
        int l = idx / (TBINS + 1);
        int bin = idx % (TBINS + 1);
        float d = (float)bin * (5.0f / (float)TBINS);
        float emb[10];
        compute_emb(d, emb);
        float w[32];
        #pragma unroll
        for (int c = 0; c < 32; c++) w[c] = 0.0f;
        for (int j = 0; j < 100; j++) {
            float h = b1[l * 100 + j];
            #pragma unroll
            for (int i = 0; i < 10; i++) h += emb[i] * W1[l * 1000 + i * 100 + j];
            h = fast_silu(h);
            const float* w2r = &W2[l * 3200 + j * 32];
            #pragma unroll
            for (int c = 0; c < 32; c++) w[c] += h * w2r[c];
        }
        const float INVS32 = 0.17677669529663687f;  // fold 1/sqrt(32)
        float* out = &g_tab[((size_t)l * (TBINS + 1) + bin) * 32];
        #pragma unroll
        for (int c = 0; c < 32; c++) out[c] = w[c] * INVS32;
        return;
    }
    b -= TAB_BLOCKS;
    int e = b * 288 + t;
    if (e < EE) atomicAdd(&g_cnt[eidx[e]], 1);
}

// ---------------- scan (two-kernel, measured ~10us) --------------------------
__global__ void scan1_kernel() {
    __shared__ int wsum[32];
    int tid = threadIdx.x;
    int b = blockIdx.x;
    int i = b * 1024 + tid;
    int v = (i < NN) ? g_cnt[i] : 0;
    int lane = tid & 31, wid = tid >> 5;
    int x = v;
    #pragma unroll
    for (int o = 1; o < 32; o <<= 1) {
        int t = __shfl_up_sync(0xffffffffu, x, o);
        if (lane >= o) x += t;
    }
    if (lane == 31) wsum[wid] = x;
    __syncthreads();
    if (wid == 0) {
        int y = wsum[lane];
        #pragma unroll
        for (int o = 1; o < 32; o <<= 1) {
            int t = __shfl_up_sync(0xffffffffu, y, o);
            if (lane >= o) y += t;
        }
        wsum[lane] = y;
    }
    __syncthreads();
    int incl = x + ((wid > 0) ? wsum[wid - 1] : 0);
    if (i < NN) g_off[i] = incl - v;
    if (tid == 1023) g_bsum[b] = incl;
}

__global__ void scan23_kernel() {
    __shared__ int addv;
    int b = blockIdx.x;
    if (threadIdx.x == 0) {
        int s = 0;
        for (int i = 0; i < b; i++) s += g_bsum[i];
        addv = s;
    }
    __syncthreads();
    int i = b * 1024 + threadIdx.x;
    if (i < NN) {
        int o = g_off[i] + addv;
        g_off[i] = o;
        g_cur[i] = o;
    }
    if (i == 0) g_off[NN] = EE;
}

// ---------------- scatter + permuted payload (64B struct, 4x STG.128) --------
__global__ __launch_bounds__(256) void scatterprep_kernel(
        const int* __restrict__ eidx,
        const float* __restrict__ edge_vec,
        const float* __restrict__ edge_attr) {
    int e = blockIdx.x * 256 + threadIdx.x;
    if (e >= EE) return;
    int dnode = eidx[e];
    int src = eidx[EE + e];
    float vx = edge_vec[3 * e + 0];
    float vy = edge_vec[3 * e + 1];
    float vz = edge_vec[3 * e + 2];
    float d = sqrtf(vx * vx + vy * vy + vz * vz + 1e-12f);
    float shv[9];
    compute_sh(vx, vy, vz, shv);
    float4 a4 = *(const float4*)(edge_attr + 4 * e);
    int pos = atomicAdd(&g_cur[dnode], 1);
    float4* dst = (float4*)(g_ep + (size_t)pos * 16);
    dst[0] = a4;
    dst[1] = make_float4(shv[0], shv[1], shv[2], shv[3]);
    dst[2] = make_float4(shv[4], shv[5], shv[6], shv[7]);
    dst[3] = make_float4(shv[8], d, __int_as_float(src), 0.0f);
}

// ---------------- fused edge-weight + aggregate + node update ---------------
// One warp per node, lanes = channels c. 3 blocks/SM (measured optimum);
// Wattr in registers; payload via uniform broadcast loads from 64B struct.
__global__ __launch_bounds__(32 * WPB, 3) void aggnode_kernel(
        const float* __restrict__ node_attr,
        const float* __restrict__ Wself,
        const float* __restrict__ Wout,
        const float* __restrict__ Wattr,
        const float* __restrict__ xin,
        float* __restrict__ xout,
        int l) {
    __shared__ float sWs[1024], sWo[1024];
    __shared__ float sX[WPB][9][32];
    __shared__ float sA[WPB][9][32];

    int t = threadIdx.x;
    int lane = t & 31;
    int wid = t >> 5;
    for (int i = t; i < 1024; i += 32 * WPB) {
        sWs[i] = Wself[l * 1024 + i];
        sWo[i] = Wout[l * 1024 + i];
    }

    // Wattr column for this lane, hoisted into registers (loop-invariant)
    float wa[13];
    #pragma unroll
    for (int i = 0; i < 13; i++) wa[i] = Wattr[l * 416 + i * 32 + lane];

    int n = blockIdx.x * WPB + wid;

    const float* tabL = g_tab + (size_t)l * (TBINS + 1) * 32;
    int j0 = g_off[n];
    int j1 = g_off[n + 1];

    float acc[9];
    #pragma unroll
    for (int k = 0; k < 9; k++) acc[k] = 0.0f;

    #pragma unroll 2
    for (int j = j0; j < j1; j++) {
        const float* epj = g_ep + (size_t)j * 16;
        float4 at = *(const float4*)epj;            // uniform broadcast
        float sh9 = (lane < 9) ? epj[4 + lane] : 0.0f;
        float d = epj[13];                          // uniform broadcast
        int src = __float_as_int(epj[14]);          // uniform broadcast

        float shk[9];
        #pragma unroll
        for (int k = 0; k < 9; k++) shk[k] = __shfl_sync(0xffffffffu, sh9, k);

        // aw[lane] = ea @ Wattr  (ea = [attr4, sh9]); weights in registers
        float aw = at.x * wa[0];
        aw = fmaf(at.y, wa[1], aw);
        aw = fmaf(at.z, wa[2], aw);
        aw = fmaf(at.w, wa[3], aw);
        #pragma unroll
        for (int k = 0; k < 9; k++) aw = fmaf(shk[k], wa[4 + k], aw);

        // radial lerp (includes 1/sqrt(32)); branch-free clamp, exact at d>=5
        float u = fminf(d * TSCALE, (float)TBINS);
        int i0 = min((int)u, TBINS - 1);
        float f = u - (float)i0;
        float a = tabL[i0 * 32 + lane];
        float b = tabL[(i0 + 1) * 32 + lane];
        float w = fmaf(f, b - a, a) * aw;

        const float* xr = xin + (size_t)src * 288 + lane;
        #pragma unroll
        for (int k = 0; k < 9; k++)
            acc[k] = fmaf(xr[k * 32], shk[k] * w, acc[k]);
    }

    // stash aggregate, then load self features (coalesced) for phase 2
    #pragma unroll
    for (int k = 0; k < 9; k++) sA[wid][k][lane] = acc[k];
    {
        const float* xself = xin + (size_t)n * 288 + lane;
        #pragma unroll
        for (int k = 0; k < 9; k++) sX[wid][k][lane] = xself[k * 32];
    }
    __syncwarp();

    // phase 2: per-warp 32x32 mixes + gating (lane = d)
    float na = node_attr[n];
    float val[9];
    #pragma unroll
    for (int k = 0; k < 9; k++) {
        float aS = 0.0f, aA = 0.0f;
        #pragma unroll
        for (int c = 0; c < 32; c++) {
            aS = fmaf(sX[wid][k][c], sWs[c * 32 + lane], aS);
            aA = fmaf(sA[wid][k][c], sWo[c * 32 + lane], aA);
        }
        val[k] = na * aS + aA;
    }
    float sig = __fdividef(1.0f, 1.0f + __expf(-val[0]));
    float* outr = xout + (size_t)n * 288 + lane;
    outr[0] = val[0] * sig;
    #pragma unroll
    for (int k = 1; k < 9; k++) outr[k * 32] = val[k] * sig;
}

// ---------------- output reduction ------------------------------------------
__global__ __launch_bounds__(288) void out_kernel(const int* __restrict__ batch,
                                                  const float* __restrict__ xfin,
                                                  float* __restrict__ out) {
    int t = threadIdx.x;
    int k = t >> 5;             // warp reads contiguous c
    int c = t & 31;
    int n0 = blockIdx.x * 64;
    int n1 = n0 + 64;
    if (n1 > NN) n1 = NN;
    float acc = 0.0f;
    int curg = batch[n0];
    const float INVS400 = 0.05f;  // 1/sqrt(400)
    for (int n = n0; n < n1; n++) {
        int g = batch[n];
        if (g != curg) {
            atomicAdd(&out[curg * 288 + c * 9 + k], acc * INVS400);
            acc = 0.0f;
            curg = g;
        }
        acc += xfin[(n * SHD + k) * CC + c];
    }
    atomicAdd(&out[curg * 288 + c * 9 + k], acc * INVS400);
}

// ---------------- launch ----------------------------------------------------
extern "C" void kernel_launch(void* const* d_in, const int* in_sizes, int n_in,
                              void* d_out, int out_size) {
    const float* node_input = (const float*)d_in[0];
    const float* node_attr  = (const float*)d_in[1];
    const float* edge_vec   = (const float*)d_in[2];
    const float* edge_attr  = (const float*)d_in[3];
    const float* W1         = (const float*)d_in[4];
    const float* b1         = (const float*)d_in[5];
    const float* W2         = (const float*)d_in[6];
    const float* Wattr      = (const float*)d_in[7];
    const float* Wself      = (const float*)d_in[8];
    const float* Wout       = (const float*)d_in[9];
    const int*   eidx       = (const int*)d_in[10];
    const int*   batch      = (const int*)d_in[11];
    float* out = (float*)d_out;

    float* bufA; cudaGetSymbolAddress((void**)&bufA, g_bufA);
    float* bufB; cudaGetSymbolAddress((void**)&bufB, g_bufB);
    int*   cntp; cudaGetSymbolAddress((void**)&cntp, g_cnt);

    cudaMemsetAsync(cntp, 0, NN * sizeof(int));

    // #1: fused transpose + radial tables + histogram
    combo_kernel<<<NN + TAB_BLOCKS + HIST_BLOCKS, 288>>>(node_input, W1, b1, W2, eidx);
    // #2,#3: exclusive scan of degrees
    scan1_kernel<<<16, 1024>>>();
    scan23_kernel<<<16, 1024>>>();
    // #4: scatter + permuted 64B payload structs
    scatterprep_kernel<<<(EE + 255) / 256, 256>>>(eidx, edge_vec, edge_attr);

    float* xin = bufA;
    float* xout = bufB;
    for (int l = 0; l < NLAYERS; l++) {
        aggnode_kernel<<<NN / WPB, 32 * WPB>>>(node_attr, Wself, Wout, Wattr,
                                               xin, xout, l);
        float* tmp = xin; xin = xout; xout = tmp;
    }

    cudaMemsetAsync(out, 0, (size_t)out_size * sizeof(float));
    out_kernel<<<(NN + 63) / 64, 288>>>(batch, xin, out);
}